// round 12
// baseline (speedup 1.0000x reference)
#include <cuda_runtime.h>
#include <cuda_bf16.h>
#include <cstdint>
#include <math.h>

#define LSEQ     2048
#define HIDDEN   2048
#define INTER    4096
#define HEADS    64
#define HEAD_DIM 64
#define STATE    64
#define KCONV    4
#define CONV_DIM (INTER + 2 * STATE)            // 4224
#define PROJ     (INTER + CONV_DIM + HEADS)     // 8384
#define W1_RPAD  8448                           // PROJ padded to 128

// ---------------- scratch ------------------------------------------------
__device__ float g_proj[(size_t)LSEQ * PROJ];
__device__ float g_conv[(size_t)LSEQ * CONV_DIM];
__device__ float g_y[(size_t)LSEQ * INTER];      // scan partial (n 0..31)
__device__ float g_y2[(size_t)LSEQ * INTER];     // scan partial (n 32..63)
__device__ float g_dtv[LSEQ * HEADS];
__device__ float g_dA[LSEQ * HEADS];
__device__ int   g_tile_ctr;
// bf16 split operands (u32 = packed bf16 pair, k-permuted layout)
__device__ uint32_t g_h_hi[(size_t)LSEQ * (HIDDEN / 2)];
__device__ uint32_t g_h_lo[(size_t)LSEQ * (HIDDEN / 2)];
__device__ uint32_t g_w1_hi[(size_t)W1_RPAD * (HIDDEN / 2)];
__device__ uint32_t g_w1_lo[(size_t)W1_RPAD * (HIDDEN / 2)];
__device__ uint32_t g_w2_hi[(size_t)HIDDEN * (INTER / 2)];
__device__ uint32_t g_w2_lo[(size_t)HIDDEN * (INTER / 2)];
__device__ uint32_t g_yn_hi[(size_t)LSEQ * (INTER / 2)];
__device__ uint32_t g_yn_lo[(size_t)LSEQ * (INTER / 2)];

// ---------------- helpers --------------------------------------------------
__device__ __forceinline__ void split_pack(float x0, float x1, uint32_t& hi, uint32_t& lo) {
    __nv_bfloat16 h0 = __float2bfloat16(x0);
    __nv_bfloat16 h1 = __float2bfloat16(x1);
    __nv_bfloat16 l0 = __float2bfloat16(x0 - __bfloat162float(h0));
    __nv_bfloat16 l1 = __float2bfloat16(x1 - __bfloat162float(h1));
    hi = (uint32_t)__bfloat16_as_ushort(h0) | ((uint32_t)__bfloat16_as_ushort(h1) << 16);
    lo = (uint32_t)__bfloat16_as_ushort(l0) | ((uint32_t)__bfloat16_as_ushort(l1) << 16);
}

__device__ __forceinline__ void mma_bf16(float* d, const uint32_t* a, const uint32_t* b) {
    asm volatile(
        "mma.sync.aligned.m16n8k16.row.col.f32.bf16.bf16.f32 "
        "{%0,%1,%2,%3}, {%4,%5,%6,%7}, {%8,%9}, {%0,%1,%2,%3};"
        : "+f"(d[0]), "+f"(d[1]), "+f"(d[2]), "+f"(d[3])
        : "r"(a[0]), "r"(a[1]), "r"(a[2]), "r"(a[3]), "r"(b[0]), "r"(b[1]));
}

__device__ __forceinline__ uint32_t smem_u32p(const void* p) {
    uint32_t a;
    asm("{ .reg .u64 t; cvta.to.shared.u64 t, %1; cvt.u32.u64 %0, t; }" : "=r"(a) : "l"(p));
    return a;
}
__device__ __forceinline__ void cp16(uint32_t dst, const void* src) {
    asm volatile("cp.async.cg.shared.global [%0], [%1], 16;" :: "r"(dst), "l"(src));
}
__device__ __forceinline__ void cp_commit() { asm volatile("cp.async.commit_group;"); }
__device__ __forceinline__ void cp_wait1()  { asm volatile("cp.async.wait_group 1;" ::: "memory"); }
__device__ __forceinline__ void cp_wait0()  { asm volatile("cp.async.wait_group 0;" ::: "memory"); }

// ---------------- convert f32 -> permuted bf16 hi/lo pairs (R5 layout) -----
__global__ void cvt_split(const float* __restrict__ in, uint32_t* __restrict__ hi,
                          uint32_t* __restrict__ lo, int R, int K)
{
    const int K2 = K >> 1;
    int jj  = blockIdx.x * blockDim.x + threadIdx.x;
    int row = blockIdx.y;
    if (jj >= K2) return;
    int g = jj >> 3, p = jj & 7;
    int jl = (g << 3) + (p >> 1) + ((p & 1) << 2);
    float a0 = 0.f, a1 = 0.f;
    if (row < R) {
        a0 = in[(size_t)row * K + 2 * jl];
        a1 = in[(size_t)row * K + 2 * jl + 1];
    }
    uint32_t h, l;
    split_pack(a0, a1, h, l);
    hi[(size_t)row * K2 + jj] = h;
    lo[(size_t)row * K2 + jj] = l;
}

// ---------------- persistent bf16x3 GEMM with dynamic tiles -----------------
// Inner stage body identical to R10 measured-best. 296 resident CTAs stream
// stages continuously across atomically-grabbed 128x128 tiles; issue leads
// consume by 2 stages even across tile boundaries (slot = global count % 3).
#define BM 128
#define BN 128
#define BKE 32
#define BUF_U32 (BM * 16)              // 2048
#define STAGE_U32 (4 * BUF_U32)        // 8192
#define GEMM_SMEM_BYTES (3 * STAGE_U32 * 4)   // 98304
#define GPERS 296

__global__ __launch_bounds__(256, 2) void gemm_bf3(
    const uint32_t* __restrict__ Ahi, const uint32_t* __restrict__ Alo,
    const uint32_t* __restrict__ Bhi, const uint32_t* __restrict__ Blo,
    float* __restrict__ C, int M, int N, int K, int ldc,
    int ntiles, int tiles_x)
{
    extern __shared__ uint32_t dsm[];
    __shared__ int ring[4];
    const int K2  = K >> 1;
    const int nst = K / BKE;
    const int tid  = threadIdx.x;
    const int wid  = tid >> 5;
    const int lane = tid & 31;
    const int wm   = wid & 1;
    const int wn   = wid >> 1;
    const int lg   = lane >> 2;
    const int lc   = lane & 3;

    const uint32_t sbase = smem_u32p(dsm);
    const int crow = tid >> 1;
    const int cj   = (tid & 1) * 2;
    const int rsw  = (crow >> 1) & 1;

    if (tid == 0) ring[0] = atomicAdd(&g_tile_ctr, 1);
    __syncthreads();
    const int t0 = ring[0];
    if (t0 >= ntiles) return;

    float acc[4][4][4];
#pragma unroll
    for (int i = 0; i < 4; ++i)
#pragma unroll
        for (int j = 0; j < 4; ++j)
#pragma unroll
            for (int qq = 0; qq < 4; ++qq) acc[i][j][qq] = 0.f;

    auto issue = [&](int tile, int s, int slot) {
        const int im0 = (tile / tiles_x) * BM;
        const int in0 = (tile % tiles_x) * BN;
        const uint32_t st = sbase + (slot * STAGE_U32) * 4;
        const size_t ga = (size_t)(im0 + crow) * K2 + (size_t)s * 16;
        const size_t gb = (size_t)(in0 + crow) * K2 + (size_t)s * 16;
#pragma unroll
        for (int c = 0; c < 2; ++c) {
            const int j  = cj + (c ^ rsw);
            const int jp = j ^ (crow & 3);
            const uint32_t d = st + (crow * 16 + jp * 4) * 4;
            cp16(d,                    Ahi + ga + j * 4);
            cp16(d + BUF_U32 * 4,      Alo + ga + j * 4);
            cp16(d + 2 * BUF_U32 * 4,  Bhi + gb + j * 4);
            cp16(d + 3 * BUF_U32 * 4,  Blo + gb + j * 4);
        }
    };

    int n_issued = 0;
    issue(t0, 0, 0); cp_commit(); n_issued = 1;
    issue(t0, 1, 1); cp_commit(); n_issued = 2;   // nst >= 64 so both in tile t0

    int q  = 0;        // consume counter (global stage index)
    int tc = t0;       // consume tile
    int sc = 0;        // stage within consume tile

    while (true) {
        if (n_issued >= q + 2) cp_wait1(); else cp_wait0();
        __syncthreads();

        // issue next stage (lead 2) if its tile is valid
        {
            int g  = n_issued / nst;
            int tn = ring[g & 3];
            if (n_issued == q + 2 && tn < ntiles) {
                issue(tn, n_issued % nst, n_issued % 3);
                cp_commit();
                n_issued++;
            }
        }
        // pre-grab tile id needed by the issue of next iteration's +2 stage
        if (tid == 0 && ((q + 3) % nst) == 0) {
            int g = (q + 3) / nst;
            ring[g & 3] = atomicAdd(&g_tile_ctr, 1);
        }

        // ---- compute stage q (tile tc), slot q%3 — body identical to R10 ----
        const uint32_t* st   = dsm + (q % 3) * STAGE_U32;
        const uint32_t* pAhi = st;
        const uint32_t* pAlo = st + BUF_U32;
        const uint32_t* pBhi = st + 2 * BUF_U32;
        const uint32_t* pBlo = st + 3 * BUF_U32;

#pragma unroll
        for (int ks = 0; ks < 2; ++ks) {
            const int jw = ks * 8 + 2 * lc;
            uint2 aH0[4], aH1[4], aL0[4], aL1[4], bH[4], bL[4];
#pragma unroll
            for (int mt = 0; mt < 4; ++mt) {
                int r0 = wm * 64 + mt * 16 + lg;
                int sx = (r0 & 3) << 2;
                int o0 = r0 * 16 + (jw ^ sx);
                int o1 = (r0 + 8) * 16 + (jw ^ sx);
                aH0[mt] = *reinterpret_cast<const uint2*>(pAhi + o0);
                aH1[mt] = *reinterpret_cast<const uint2*>(pAhi + o1);
                aL0[mt] = *reinterpret_cast<const uint2*>(pAlo + o0);
                aL1[mt] = *reinterpret_cast<const uint2*>(pAlo + o1);
            }
#pragma unroll
            for (int nt = 0; nt < 4; ++nt) {
                int rb = wn * 32 + nt * 8 + lg;
                int ob = rb * 16 + (jw ^ ((rb & 3) << 2));
                bH[nt] = *reinterpret_cast<const uint2*>(pBhi + ob);
                bL[nt] = *reinterpret_cast<const uint2*>(pBlo + ob);
            }
#pragma unroll
            for (int mt = 0; mt < 4; ++mt) {
                uint32_t ah[4] = {aH0[mt].x, aH1[mt].x, aH0[mt].y, aH1[mt].y};
#pragma unroll
                for (int nt = 0; nt < 4; ++nt) {
                    uint32_t bh[2] = {bH[nt].x, bH[nt].y};
                    mma_bf16(acc[mt][nt], ah, bh);
                }
            }
#pragma unroll
            for (int mt = 0; mt < 4; ++mt) {
                uint32_t ah[4] = {aH0[mt].x, aH1[mt].x, aH0[mt].y, aH1[mt].y};
#pragma unroll
                for (int nt = 0; nt < 4; ++nt) {
                    uint32_t bl[2] = {bL[nt].x, bL[nt].y};
                    mma_bf16(acc[mt][nt], ah, bl);
                }
            }
#pragma unroll
            for (int mt = 0; mt < 4; ++mt) {
                uint32_t al[4] = {aL0[mt].x, aL1[mt].x, aL0[mt].y, aL1[mt].y};
#pragma unroll
                for (int nt = 0; nt < 4; ++nt) {
                    uint32_t bh[2] = {bH[nt].x, bH[nt].y};
                    mma_bf16(acc[mt][nt], al, bh);
                }
            }
        }

        if (sc == nst - 1) {
            // epilogue for tile tc, then advance to next grabbed tile
            const int em0 = (tc / tiles_x) * BM;
            const int en0 = (tc % tiles_x) * BN;
#pragma unroll
            for (int mt = 0; mt < 4; ++mt) {
                int r0 = em0 + wm * 64 + mt * 16 + lg;
#pragma unroll
                for (int nt = 0; nt < 4; ++nt) {
                    int gc = en0 + wn * 32 + nt * 8 + lc * 2;
                    if (gc < N) {
                        *reinterpret_cast<float2*>(&C[(size_t)r0 * ldc + gc]) =
                            make_float2(acc[mt][nt][0], acc[mt][nt][1]);
                        *reinterpret_cast<float2*>(&C[(size_t)(r0 + 8) * ldc + gc]) =
                            make_float2(acc[mt][nt][2], acc[mt][nt][3]);
                    }
                    acc[mt][nt][0] = 0.f; acc[mt][nt][1] = 0.f;
                    acc[mt][nt][2] = 0.f; acc[mt][nt][3] = 0.f;
                }
            }
            int gseq = (q + 1) / nst;
            tc = ring[gseq & 3];
            if (tc >= ntiles) break;
            sc = 0;
        } else {
            sc++;
        }
        q++;
    }
}

// ---------------- conv + silu ---------------------------------------------
__global__ void conv_silu_kernel(const float* __restrict__ conv_w,
                                 const float* __restrict__ conv_b)
{
    int idx = blockIdx.x * blockDim.x + threadIdx.x;
    if (idx >= LSEQ * CONV_DIM) return;
    int c = idx % CONV_DIM;
    int t = idx / CONV_DIM;
    const float4 w = *reinterpret_cast<const float4*>(&conv_w[c * 4]);
    const float* col = g_proj + INTER + c;
    float acc = conv_b[c];
    if (t - 3 >= 0) acc = fmaf(col[(size_t)(t - 3) * PROJ], w.x, acc);
    if (t - 2 >= 0) acc = fmaf(col[(size_t)(t - 2) * PROJ], w.y, acc);
    if (t - 1 >= 0) acc = fmaf(col[(size_t)(t - 1) * PROJ], w.z, acc);
    acc = fmaf(col[(size_t)t * PROJ], w.w, acc);
    g_conv[idx] = acc / (1.f + expf(-acc));
}

// ---------------- dt transform ---------------------------------------------
__global__ void dt_kernel(const float* __restrict__ dt_bias,
                          const float* __restrict__ A_log)
{
    int idx = blockIdx.x * blockDim.x + threadIdx.x;
    if (idx >= LSEQ * HEADS) return;
    int h = idx & (HEADS - 1);
    int t = idx >> 6;
    float z = g_proj[(size_t)t * PROJ + INTER + CONV_DIM + h] + dt_bias[h];
    float d = (z > 20.f) ? z : log1pf(expf(z));
    float A = -expf(A_log[h]);
    g_dtv[idx] = d;
    g_dA[idx]  = expf(d * A);
}

// ---------------- selective scan v3 (measured best) --------------------------
#define TCH 8
#define NCH (LSEQ / TCH)
__global__ __launch_bounds__(128) void scan_kernel(const float* __restrict__ D)
{
    const int h   = blockIdx.x >> 2;
    const int ph  = (blockIdx.x >> 1) & 1;
    const int nh  = blockIdx.x & 1;
    const int tid = threadIdx.x;
    const int pl  = tid >> 2;
    const int q   = tid & 3;
    const int n0  = q * 8;
    const float Dh = D[h];
    float* yout = nh ? g_y2 : g_y;

    __shared__ float sB[2][TCH][32], sC[2][TCH][32], sX[2][TCH][32];
    __shared__ float sDT[2][TCH], sDA[2][TCH];

    const int tl   = tid >> 4;
    const int col2 = tid & 15;

    {
        const float* rowp = g_conv + (size_t)tl * CONV_DIM;
        *reinterpret_cast<float2*>(&sB[0][tl][col2 * 2]) =
            *reinterpret_cast<const float2*>(&rowp[INTER + nh * 32 + col2 * 2]);
        *reinterpret_cast<float2*>(&sC[0][tl][col2 * 2]) =
            *reinterpret_cast<const float2*>(&rowp[INTER + STATE + nh * 32 + col2 * 2]);
        *reinterpret_cast<float2*>(&sX[0][tl][col2 * 2]) =
            *reinterpret_cast<const float2*>(&rowp[h * HEAD_DIM + ph * 32 + col2 * 2]);
        if (tid < TCH)           sDT[0][tid]       = g_dtv[tid * HEADS + h];
        else if (tid < 2 * TCH)  sDA[0][tid - TCH] = g_dA[(tid - TCH) * HEADS + h];
    }
    __syncthreads();

    float s[8];
#pragma unroll
    for (int i = 0; i < 8; ++i) s[i] = 0.f;

    for (int c = 0; c < NCH; ++c) {
        const int buf = c & 1;
        const int t0  = c * TCH;
        const bool more = (c + 1 < NCH);

        float2 nB, nC, nX; float nS = 0.f;
        if (more) {
            const float* rowp = g_conv + (size_t)(t0 + TCH + tl) * CONV_DIM;
            nB = *reinterpret_cast<const float2*>(&rowp[INTER + nh * 32 + col2 * 2]);
            nC = *reinterpret_cast<const float2*>(&rowp[INTER + STATE + nh * 32 + col2 * 2]);
            nX = *reinterpret_cast<const float2*>(&rowp[h * HEAD_DIM + ph * 32 + col2 * 2]);
            if (tid < TCH)           nS = g_dtv[(t0 + TCH + tid) * HEADS + h];
            else if (tid < 2 * TCH)  nS = g_dA[(t0 + TCH + tid - TCH) * HEADS + h];
        }

#pragma unroll
        for (int k = 0; k < TCH; ++k) {
            const float a   = sDA[buf][k];
            const float dtv = sDT[buf][k];
            const float xv  = sX[buf][k][pl];
            const float dtx = dtv * xv;
            float4 b0 = *reinterpret_cast<const float4*>(&sB[buf][k][n0]);
            float4 b1 = *reinterpret_cast<const float4*>(&sB[buf][k][n0 + 4]);
            float4 c0 = *reinterpret_cast<const float4*>(&sC[buf][k][n0]);
            float4 c1 = *reinterpret_cast<const float4*>(&sC[buf][k][n0 + 4]);
            s[0] = fmaf(a, s[0], dtx * b0.x);
            s[1] = fmaf(a, s[1], dtx * b0.y);
            s[2] = fmaf(a, s[2], dtx * b0.z);
            s[3] = fmaf(a, s[3], dtx * b0.w);
            s[4] = fmaf(a, s[4], dtx * b1.x);
            s[5] = fmaf(a, s[5], dtx * b1.y);
            s[6] = fmaf(a, s[6], dtx * b1.z);
            s[7] = fmaf(a, s[7], dtx * b1.w);
            float e0 = fmaf(s[1], c0.y, s[0] * c0.x);
            float e1 = fmaf(s[3], c0.w, s[2] * c0.z);
            float e2 = fmaf(s[5], c1.y, s[4] * c1.x);
            float e3 = fmaf(s[7], c1.w, s[6] * c1.z);
            float accv = (e0 + e1) + (e2 + e3);
            accv += __shfl_xor_sync(0xffffffffu, accv, 1);
            accv += __shfl_xor_sync(0xffffffffu, accv, 2);
            if (q == 0) {
                float o = accv + (nh == 0 ? Dh * xv : 0.f);
                yout[(size_t)(t0 + k) * INTER + h * HEAD_DIM + ph * 32 + pl] = o;
            }
        }

        if (more) {
            const int nb = buf ^ 1;
            *reinterpret_cast<float2*>(&sB[nb][tl][col2 * 2]) = nB;
            *reinterpret_cast<float2*>(&sC[nb][tl][col2 * 2]) = nC;
            *reinterpret_cast<float2*>(&sX[nb][tl][col2 * 2]) = nX;
            if (tid < TCH)           sDT[nb][tid]       = nS;
            else if (tid < 2 * TCH)  sDA[nb][tid - TCH] = nS;
        }
        __syncthreads();
    }
}

// ---------------- RMSNorm * silu(gate) -> bf16 hi/lo (R5 permutation) ---------
__global__ __launch_bounds__(256) void norm_gate_cvt(const float* __restrict__ nw)
{
    const int t = blockIdx.x;
    const float* y1 = g_y  + (size_t)t * INTER;
    const float* y2 = g_y2 + (size_t)t * INTER;
    const float* gp = g_proj + (size_t)t * PROJ;
    __shared__ float red[256];
    float ss = 0.f;
    for (int c = threadIdx.x; c < INTER; c += 256) {
        float v = y1[c] + y2[c];
        ss = fmaf(v, v, ss);
    }
    red[threadIdx.x] = ss;
    __syncthreads();
    for (int off = 128; off > 0; off >>= 1) {
        if (threadIdx.x < off) red[threadIdx.x] += red[threadIdx.x + off];
        __syncthreads();
    }
    const float r = rsqrtf(red[0] / (float)INTER + 1e-6f);

    const int K2 = INTER / 2;
    for (int J = threadIdx.x; J < K2; J += 256) {
        int g = J >> 3, p = J & 7;
        int jl = (g << 3) + (p >> 1) + ((p & 1) << 2);
        int c0 = 2 * jl;
        float ga = gp[c0], gb = gp[c0 + 1];
        float v0 = (y1[c0] + y2[c0]) * r * nw[c0] * (ga / (1.f + expf(-ga)));
        float v1 = (y1[c0 + 1] + y2[c0 + 1]) * r * nw[c0 + 1] * (gb / (1.f + expf(-gb)));
        uint32_t h, l;
        split_pack(v0, v1, h, l);
        g_yn_hi[(size_t)t * K2 + J] = h;
        g_yn_lo[(size_t)t * K2 + J] = l;
    }
}

// ---------------- launch ------------------------------------------------------
extern "C" void kernel_launch(void* const* d_in, const int* in_sizes, int n_in,
                              void* d_out, int out_size)
{
    const float* hidden     = (const float*)d_in[0];
    const float* in_proj_w  = (const float*)d_in[1];
    const float* conv_w     = (const float*)d_in[2];
    const float* conv_b     = (const float*)d_in[3];
    const float* dt_bias    = (const float*)d_in[4];
    const float* A_log      = (const float*)d_in[5];
    const float* Dv         = (const float*)d_in[6];
    const float* norm_w     = (const float*)d_in[7];
    const float* out_proj_w = (const float*)d_in[8];
    float* out = (float*)d_out;

    float* p_proj = nullptr;
    cudaGetSymbolAddress((void**)&p_proj, g_proj);
    int* p_ctr = nullptr;
    cudaGetSymbolAddress((void**)&p_ctr, g_tile_ctr);
    uint32_t *p_hhi, *p_hlo, *p_w1hi, *p_w1lo, *p_w2hi, *p_w2lo, *p_ynhi, *p_ynlo;
    cudaGetSymbolAddress((void**)&p_hhi, g_h_hi);
    cudaGetSymbolAddress((void**)&p_hlo, g_h_lo);
    cudaGetSymbolAddress((void**)&p_w1hi, g_w1_hi);
    cudaGetSymbolAddress((void**)&p_w1lo, g_w1_lo);
    cudaGetSymbolAddress((void**)&p_w2hi, g_w2_hi);
    cudaGetSymbolAddress((void**)&p_w2lo, g_w2_lo);
    cudaGetSymbolAddress((void**)&p_ynhi, g_yn_hi);
    cudaGetSymbolAddress((void**)&p_ynlo, g_yn_lo);

    cudaFuncSetAttribute(gemm_bf3, cudaFuncAttributeMaxDynamicSharedMemorySize, GEMM_SMEM_BYTES);

    cvt_split<<<dim3(HIDDEN / 2 / 256, LSEQ), 256>>>(hidden, p_hhi, p_hlo, LSEQ, HIDDEN);
    cvt_split<<<dim3(HIDDEN / 2 / 256, W1_RPAD), 256>>>(in_proj_w, p_w1hi, p_w1lo, PROJ, HIDDEN);
    cvt_split<<<dim3(INTER / 2 / 256, HIDDEN), 256>>>(out_proj_w, p_w2hi, p_w2lo, HIDDEN, INTER);

    // GEMM1: proj = hidden @ in_proj_w^T : M=2048, N=8384 (pad 8448), K=2048
    {
        int tiles_x = W1_RPAD / BN;              // 66
        int ntiles  = tiles_x * (LSEQ / BM);     // 1056
        cudaMemsetAsync(p_ctr, 0, sizeof(int));
        gemm_bf3<<<GPERS, 256, GEMM_SMEM_BYTES>>>(
            p_hhi, p_hlo, p_w1hi, p_w1lo, p_proj,
            LSEQ, PROJ, HIDDEN, PROJ, ntiles, tiles_x);
    }

    {
        int total = LSEQ * CONV_DIM;
        conv_silu_kernel<<<(total + 255) / 256, 256>>>(conv_w, conv_b);
    }
    {
        int total = LSEQ * HEADS;
        dt_kernel<<<(total + 255) / 256, 256>>>(dt_bias, A_log);
    }
    scan_kernel<<<HEADS * 4, 128>>>(Dv);
    norm_gate_cvt<<<LSEQ, 256>>>(norm_w);

    // GEMM2: out = y' @ out_proj_w^T : M=2048, N=2048, K=4096
    {
        int tiles_x = HIDDEN / BN;               // 16
        int ntiles  = tiles_x * (LSEQ / BM);     // 256
        cudaMemsetAsync(p_ctr, 0, sizeof(int));
        gemm_bf3<<<GPERS, 256, GEMM_SMEM_BYTES>>>(
            p_ynhi, p_ynlo, p_w2hi, p_w2lo, out,
            LSEQ, HIDDEN, INTER, HIDDEN, ntiles, tiles_x);
    }
}

// round 13
// speedup vs baseline: 1.0650x; 1.0650x over previous
#include <cuda_runtime.h>
#include <cuda_bf16.h>
#include <cstdint>
#include <math.h>

#define LSEQ     2048
#define HIDDEN   2048
#define INTER    4096
#define HEADS    64
#define HEAD_DIM 64
#define STATE    64
#define KCONV    4
#define CONV_DIM (INTER + 2 * STATE)            // 4224
#define PROJ     (INTER + CONV_DIM + HEADS)     // 8384
#define W1_RPAD  8448                           // PROJ padded to 128

// ---------------- scratch ------------------------------------------------
__device__ float g_proj[(size_t)LSEQ * PROJ];
__device__ float g_conv[(size_t)LSEQ * CONV_DIM];
__device__ float g_y[(size_t)LSEQ * INTER];
__device__ float g_dtv[LSEQ * HEADS];
__device__ float g_dA[LSEQ * HEADS];
// bf16 split operands (u32 = packed bf16 pair, k-permuted layout)
__device__ uint32_t g_h_hi[(size_t)LSEQ * (HIDDEN / 2)];
__device__ uint32_t g_h_lo[(size_t)LSEQ * (HIDDEN / 2)];
__device__ uint32_t g_w1_hi[(size_t)W1_RPAD * (HIDDEN / 2)];
__device__ uint32_t g_w1_lo[(size_t)W1_RPAD * (HIDDEN / 2)];
__device__ uint32_t g_w2_hi[(size_t)HIDDEN * (INTER / 2)];
__device__ uint32_t g_w2_lo[(size_t)HIDDEN * (INTER / 2)];
__device__ uint32_t g_yn_hi[(size_t)LSEQ * (INTER / 2)];
__device__ uint32_t g_yn_lo[(size_t)LSEQ * (INTER / 2)];

// ---------------- helpers --------------------------------------------------
__device__ __forceinline__ void split_pack(float x0, float x1, uint32_t& hi, uint32_t& lo) {
    __nv_bfloat16 h0 = __float2bfloat16(x0);
    __nv_bfloat16 h1 = __float2bfloat16(x1);
    __nv_bfloat16 l0 = __float2bfloat16(x0 - __bfloat162float(h0));
    __nv_bfloat16 l1 = __float2bfloat16(x1 - __bfloat162float(h1));
    hi = (uint32_t)__bfloat16_as_ushort(h0) | ((uint32_t)__bfloat16_as_ushort(h1) << 16);
    lo = (uint32_t)__bfloat16_as_ushort(l0) | ((uint32_t)__bfloat16_as_ushort(l1) << 16);
}

__device__ __forceinline__ void mma_bf16(float* d, const uint32_t* a, const uint32_t* b) {
    asm volatile(
        "mma.sync.aligned.m16n8k16.row.col.f32.bf16.bf16.f32 "
        "{%0,%1,%2,%3}, {%4,%5,%6,%7}, {%8,%9}, {%0,%1,%2,%3};"
        : "+f"(d[0]), "+f"(d[1]), "+f"(d[2]), "+f"(d[3])
        : "r"(a[0]), "r"(a[1]), "r"(a[2]), "r"(a[3]), "r"(b[0]), "r"(b[1]));
}

__device__ __forceinline__ uint32_t smem_u32p(const void* p) {
    uint32_t a;
    asm("{ .reg .u64 t; cvta.to.shared.u64 t, %1; cvt.u32.u64 %0, t; }" : "=r"(a) : "l"(p));
    return a;
}
__device__ __forceinline__ void cp16(uint32_t dst, const void* src) {
    asm volatile("cp.async.cg.shared.global [%0], [%1], 16;" :: "r"(dst), "l"(src));
}
__device__ __forceinline__ void cp_commit() { asm volatile("cp.async.commit_group;"); }
__device__ __forceinline__ void cp_wait1()  { asm volatile("cp.async.wait_group 1;" ::: "memory"); }
__device__ __forceinline__ void cp_wait0()  { asm volatile("cp.async.wait_group 0;" ::: "memory"); }

// ---------------- convert f32 -> permuted bf16 hi/lo pairs (R5 layout) -----
__global__ void cvt_split(const float* __restrict__ in, uint32_t* __restrict__ hi,
                          uint32_t* __restrict__ lo, int R, int K)
{
    const int K2 = K >> 1;
    int jj  = blockIdx.x * blockDim.x + threadIdx.x;
    int row = blockIdx.y;
    if (jj >= K2) return;
    int g = jj >> 3, p = jj & 7;
    int jl = (g << 3) + (p >> 1) + ((p & 1) << 2);
    float a0 = 0.f, a1 = 0.f;
    if (row < R) {
        a0 = in[(size_t)row * K + 2 * jl];
        a1 = in[(size_t)row * K + 2 * jl + 1];
    }
    uint32_t h, l;
    split_pack(a0, a1, h, l);
    hi[(size_t)row * K2 + jj] = h;
    lo[(size_t)row * K2 + jj] = l;
}

// ---------------- bf16x3 GEMM (R10 measured best, unchanged) ----------------
#define BM 128
#define BN 128
#define BKE 32
#define BUF_U32 (BM * 16)              // 2048
#define STAGE_U32 (4 * BUF_U32)        // 8192
#define GEMM_SMEM_BYTES (3 * STAGE_U32 * 4)   // 98304

__global__ __launch_bounds__(256, 2) void gemm_bf3(
    const uint32_t* __restrict__ Ahi, const uint32_t* __restrict__ Alo,
    const uint32_t* __restrict__ Bhi, const uint32_t* __restrict__ Blo,
    float* __restrict__ C, int M, int N, int K)
{
    extern __shared__ uint32_t dsm[];
    const int K2  = K >> 1;
    const int nst = K / BKE;
    const int tid  = threadIdx.x;
    const int wid  = tid >> 5;
    const int lane = tid & 31;
    const int wm   = wid & 1;
    const int wn   = wid >> 1;
    const int m0   = blockIdx.y * BM;
    const int n0   = blockIdx.x * BN;
    const int lg   = lane >> 2;
    const int lc   = lane & 3;

    const uint32_t sbase = smem_u32p(dsm);
    const int crow = tid >> 1;
    const int cj   = (tid & 1) * 2;
    const int rsw  = (crow >> 1) & 1;

    float acc[4][4][4];
#pragma unroll
    for (int i = 0; i < 4; ++i)
#pragma unroll
        for (int j = 0; j < 4; ++j)
#pragma unroll
            for (int q = 0; q < 4; ++q) acc[i][j][q] = 0.f;

    auto issue = [&](int s) {
        const uint32_t st = sbase + ((s % 3) * STAGE_U32) * 4;
        const size_t ga = (size_t)(m0 + crow) * K2 + (size_t)s * 16;
        const size_t gb = (size_t)(n0 + crow) * K2 + (size_t)s * 16;
#pragma unroll
        for (int c = 0; c < 2; ++c) {
            const int j  = cj + (c ^ rsw);
            const int jp = j ^ (crow & 3);
            const uint32_t d = st + (crow * 16 + jp * 4) * 4;
            cp16(d,                    Ahi + ga + j * 4);
            cp16(d + BUF_U32 * 4,      Alo + ga + j * 4);
            cp16(d + 2 * BUF_U32 * 4,  Bhi + gb + j * 4);
            cp16(d + 3 * BUF_U32 * 4,  Blo + gb + j * 4);
        }
    };

    issue(0); cp_commit();
    issue(1); cp_commit();

    for (int s = 0; s < nst; ++s) {
        if (s < nst - 1) cp_wait1(); else cp_wait0();
        __syncthreads();
        if (s + 2 < nst) { issue(s + 2); cp_commit(); }

        const uint32_t* st   = dsm + (s % 3) * STAGE_U32;
        const uint32_t* pAhi = st;
        const uint32_t* pAlo = st + BUF_U32;
        const uint32_t* pBhi = st + 2 * BUF_U32;
        const uint32_t* pBlo = st + 3 * BUF_U32;

#pragma unroll
        for (int ks = 0; ks < 2; ++ks) {
            const int jw = ks * 8 + 2 * lc;
            uint2 aH0[4], aH1[4], aL0[4], aL1[4], bH[4], bL[4];
#pragma unroll
            for (int mt = 0; mt < 4; ++mt) {
                int r0 = wm * 64 + mt * 16 + lg;
                int sx = (r0 & 3) << 2;
                int o0 = r0 * 16 + (jw ^ sx);
                int o1 = (r0 + 8) * 16 + (jw ^ sx);
                aH0[mt] = *reinterpret_cast<const uint2*>(pAhi + o0);
                aH1[mt] = *reinterpret_cast<const uint2*>(pAhi + o1);
                aL0[mt] = *reinterpret_cast<const uint2*>(pAlo + o0);
                aL1[mt] = *reinterpret_cast<const uint2*>(pAlo + o1);
            }
#pragma unroll
            for (int nt = 0; nt < 4; ++nt) {
                int rb = wn * 32 + nt * 8 + lg;
                int ob = rb * 16 + (jw ^ ((rb & 3) << 2));
                bH[nt] = *reinterpret_cast<const uint2*>(pBhi + ob);
                bL[nt] = *reinterpret_cast<const uint2*>(pBlo + ob);
            }
#pragma unroll
            for (int mt = 0; mt < 4; ++mt) {
                uint32_t ah[4] = {aH0[mt].x, aH1[mt].x, aH0[mt].y, aH1[mt].y};
#pragma unroll
                for (int nt = 0; nt < 4; ++nt) {
                    uint32_t bh[2] = {bH[nt].x, bH[nt].y};
                    mma_bf16(acc[mt][nt], ah, bh);
                }
            }
#pragma unroll
            for (int mt = 0; mt < 4; ++mt) {
                uint32_t ah[4] = {aH0[mt].x, aH1[mt].x, aH0[mt].y, aH1[mt].y};
#pragma unroll
                for (int nt = 0; nt < 4; ++nt) {
                    uint32_t bl[2] = {bL[nt].x, bL[nt].y};
                    mma_bf16(acc[mt][nt], ah, bl);
                }
            }
#pragma unroll
            for (int mt = 0; mt < 4; ++mt) {
                uint32_t al[4] = {aL0[mt].x, aL1[mt].x, aL0[mt].y, aL1[mt].y};
#pragma unroll
                for (int nt = 0; nt < 4; ++nt) {
                    uint32_t bh[2] = {bH[nt].x, bH[nt].y};
                    mma_bf16(acc[mt][nt], al, bh);
                }
            }
        }
    }

#pragma unroll
    for (int mt = 0; mt < 4; ++mt) {
        int r0 = m0 + wm * 64 + mt * 16 + lg;
#pragma unroll
        for (int nt = 0; nt < 4; ++nt) {
            int gc = n0 + wn * 32 + nt * 8 + lc * 2;
            if (gc < N) {
                *reinterpret_cast<float2*>(&C[(size_t)r0 * N + gc]) =
                    make_float2(acc[mt][nt][0], acc[mt][nt][1]);
                *reinterpret_cast<float2*>(&C[(size_t)(r0 + 8) * N + gc]) =
                    make_float2(acc[mt][nt][2], acc[mt][nt][3]);
            }
        }
    }
}

// ---------------- fused conv+silu and dt transform --------------------------
__global__ void conv_dt_kernel(const float* __restrict__ conv_w,
                               const float* __restrict__ conv_b,
                               const float* __restrict__ dt_bias,
                               const float* __restrict__ A_log)
{
    int idx = blockIdx.x * blockDim.x + threadIdx.x;
    if (idx < LSEQ * CONV_DIM) {
        int c = idx % CONV_DIM;
        int t = idx / CONV_DIM;
        const float4 w = *reinterpret_cast<const float4*>(&conv_w[c * 4]);
        const float* col = g_proj + INTER + c;
        float acc = conv_b[c];
        if (t - 3 >= 0) acc = fmaf(col[(size_t)(t - 3) * PROJ], w.x, acc);
        if (t - 2 >= 0) acc = fmaf(col[(size_t)(t - 2) * PROJ], w.y, acc);
        if (t - 1 >= 0) acc = fmaf(col[(size_t)(t - 1) * PROJ], w.z, acc);
        acc = fmaf(col[(size_t)t * PROJ], w.w, acc);
        g_conv[idx] = acc / (1.f + expf(-acc));
    } else {
        int j = idx - LSEQ * CONV_DIM;
        if (j >= LSEQ * HEADS) return;
        int h = j & (HEADS - 1);
        int t = j >> 6;
        float z = g_proj[(size_t)t * PROJ + INTER + CONV_DIM + h] + dt_bias[h];
        float d = (z > 20.f) ? z : log1pf(expf(z));
        float A = -expf(A_log[h]);
        g_dtv[j] = d;
        g_dA[j]  = expf(d * A);
    }
}

// ---------------- selective scan v3b -----------------------------------------
// grid = 64h x 2 p-halves = 128 CTAs, 256 threads = 32p x 8q (8 states each).
// Full n=64 reduced in-warp (3 shfls) -> single y buffer.
#define TCH 8
#define NCH (LSEQ / TCH)
__global__ __launch_bounds__(256) void scan_kernel(const float* __restrict__ D)
{
    const int h   = blockIdx.x >> 1;
    const int ph  = blockIdx.x & 1;
    const int tid = threadIdx.x;
    const int pl  = tid >> 3;                // 0..31
    const int q   = tid & 7;                 // 0..7
    const int n0  = q * 8;                   // 8 states within n=64
    const float Dh = D[h];

    __shared__ float sBC[2][TCH][128];       // [0..63]=B, [64..127]=C
    __shared__ float sX[2][TCH][32];
    __shared__ float sDT[2][TCH], sDA[2][TCH];

    const int tl  = tid >> 5;                // 0..7 (timestep row)
    const int col = tid & 31;                // 0..31 (float4 slot: B 0-15, C 16-31)

    {
        const float* rowp = g_conv + (size_t)tl * CONV_DIM;
        *reinterpret_cast<float4*>(&sBC[0][tl][col * 4]) =
            *reinterpret_cast<const float4*>(&rowp[INTER + col * 4]);
        if (tid < 64) {                      // X: 8 rows x 8 float4
            int tr = tid >> 3, cc = (tid & 7) * 4;
            *reinterpret_cast<float4*>(&sX[0][tr][cc]) =
                *reinterpret_cast<const float4*>(
                    &g_conv[(size_t)tr * CONV_DIM + h * HEAD_DIM + ph * 32 + cc]);
        }
        if (tid >= 64 && tid < 64 + TCH)            sDT[0][tid - 64] = g_dtv[(tid - 64) * HEADS + h];
        else if (tid >= 80 && tid < 80 + TCH)       sDA[0][tid - 80] = g_dA[(tid - 80) * HEADS + h];
    }
    __syncthreads();

    float s[8];
#pragma unroll
    for (int i = 0; i < 8; ++i) s[i] = 0.f;

    for (int c = 0; c < NCH; ++c) {
        const int buf = c & 1;
        const int t0  = c * TCH;
        const bool more = (c + 1 < NCH);

        float4 nBC, nX; float nDT = 0.f, nDA = 0.f;
        if (more) {
            const float* rowp = g_conv + (size_t)(t0 + TCH + tl) * CONV_DIM;
            nBC = *reinterpret_cast<const float4*>(&rowp[INTER + col * 4]);
            if (tid < 64) {
                int tr = tid >> 3, cc = (tid & 7) * 4;
                nX = *reinterpret_cast<const float4*>(
                    &g_conv[(size_t)(t0 + TCH + tr) * CONV_DIM + h * HEAD_DIM + ph * 32 + cc]);
            }
            if (tid >= 64 && tid < 64 + TCH)      nDT = g_dtv[(t0 + TCH + tid - 64) * HEADS + h];
            else if (tid >= 80 && tid < 80 + TCH) nDA = g_dA[(t0 + TCH + tid - 80) * HEADS + h];
        }

#pragma unroll
        for (int k = 0; k < TCH; ++k) {
            const float a   = sDA[buf][k];
            const float dtv = sDT[buf][k];
            const float xv  = sX[buf][k][pl];
            const float dtx = dtv * xv;
            float4 b0 = *reinterpret_cast<const float4*>(&sBC[buf][k][n0]);
            float4 b1 = *reinterpret_cast<const float4*>(&sBC[buf][k][n0 + 4]);
            float4 c0 = *reinterpret_cast<const float4*>(&sBC[buf][k][64 + n0]);
            float4 c1 = *reinterpret_cast<const float4*>(&sBC[buf][k][64 + n0 + 4]);
            s[0] = fmaf(a, s[0], dtx * b0.x);
            s[1] = fmaf(a, s[1], dtx * b0.y);
            s[2] = fmaf(a, s[2], dtx * b0.z);
            s[3] = fmaf(a, s[3], dtx * b0.w);
            s[4] = fmaf(a, s[4], dtx * b1.x);
            s[5] = fmaf(a, s[5], dtx * b1.y);
            s[6] = fmaf(a, s[6], dtx * b1.z);
            s[7] = fmaf(a, s[7], dtx * b1.w);
            float e0 = fmaf(s[1], c0.y, s[0] * c0.x);
            float e1 = fmaf(s[3], c0.w, s[2] * c0.z);
            float e2 = fmaf(s[5], c1.y, s[4] * c1.x);
            float e3 = fmaf(s[7], c1.w, s[6] * c1.z);
            float accv = (e0 + e1) + (e2 + e3);
            accv += __shfl_xor_sync(0xffffffffu, accv, 1);
            accv += __shfl_xor_sync(0xffffffffu, accv, 2);
            accv += __shfl_xor_sync(0xffffffffu, accv, 4);
            if (q == 0)
                g_y[(size_t)(t0 + k) * INTER + h * HEAD_DIM + ph * 32 + pl] =
                    accv + Dh * xv;
        }

        if (more) {
            const int nb = buf ^ 1;
            *reinterpret_cast<float4*>(&sBC[nb][tl][col * 4]) = nBC;
            if (tid < 64) {
                int tr = tid >> 3, cc = (tid & 7) * 4;
                *reinterpret_cast<float4*>(&sX[nb][tr][cc]) = nX;
            }
            if (tid >= 64 && tid < 64 + TCH)      sDT[nb][tid - 64] = nDT;
            else if (tid >= 80 && tid < 80 + TCH) sDA[nb][tid - 80] = nDA;
        }
        __syncthreads();
    }
}

// ---------------- RMSNorm * silu(gate) -> bf16 hi/lo (R5 permutation) ---------
__global__ __launch_bounds__(256) void norm_gate_cvt(const float* __restrict__ nw)
{
    const int t = blockIdx.x;
    const float* y1 = g_y + (size_t)t * INTER;
    const float* gp = g_proj + (size_t)t * PROJ;
    __shared__ float red[256];
    float ss = 0.f;
    for (int c = threadIdx.x; c < INTER; c += 256) {
        float v = y1[c];
        ss = fmaf(v, v, ss);
    }
    red[threadIdx.x] = ss;
    __syncthreads();
    for (int off = 128; off > 0; off >>= 1) {
        if (threadIdx.x < off) red[threadIdx.x] += red[threadIdx.x + off];
        __syncthreads();
    }
    const float r = rsqrtf(red[0] / (float)INTER + 1e-6f);

    const int K2 = INTER / 2;
    for (int J = threadIdx.x; J < K2; J += 256) {
        int g = J >> 3, p = J & 7;
        int jl = (g << 3) + (p >> 1) + ((p & 1) << 2);
        int c0 = 2 * jl;
        float ga = gp[c0], gb = gp[c0 + 1];
        float v0 = y1[c0] * r * nw[c0] * (ga / (1.f + expf(-ga)));
        float v1 = y1[c0 + 1] * r * nw[c0 + 1] * (gb / (1.f + expf(-gb)));
        uint32_t h, l;
        split_pack(v0, v1, h, l);
        g_yn_hi[(size_t)t * K2 + J] = h;
        g_yn_lo[(size_t)t * K2 + J] = l;
    }
}

// ---------------- launch ------------------------------------------------------
extern "C" void kernel_launch(void* const* d_in, const int* in_sizes, int n_in,
                              void* d_out, int out_size)
{
    const float* hidden     = (const float*)d_in[0];
    const float* in_proj_w  = (const float*)d_in[1];
    const float* conv_w     = (const float*)d_in[2];
    const float* conv_b     = (const float*)d_in[3];
    const float* dt_bias    = (const float*)d_in[4];
    const float* A_log      = (const float*)d_in[5];
    const float* Dv         = (const float*)d_in[6];
    const float* norm_w     = (const float*)d_in[7];
    const float* out_proj_w = (const float*)d_in[8];
    float* out = (float*)d_out;

    float* p_proj = nullptr;
    cudaGetSymbolAddress((void**)&p_proj, g_proj);
    uint32_t *p_hhi, *p_hlo, *p_w1hi, *p_w1lo, *p_w2hi, *p_w2lo, *p_ynhi, *p_ynlo;
    cudaGetSymbolAddress((void**)&p_hhi, g_h_hi);
    cudaGetSymbolAddress((void**)&p_hlo, g_h_lo);
    cudaGetSymbolAddress((void**)&p_w1hi, g_w1_hi);
    cudaGetSymbolAddress((void**)&p_w1lo, g_w1_lo);
    cudaGetSymbolAddress((void**)&p_w2hi, g_w2_hi);
    cudaGetSymbolAddress((void**)&p_w2lo, g_w2_lo);
    cudaGetSymbolAddress((void**)&p_ynhi, g_yn_hi);
    cudaGetSymbolAddress((void**)&p_ynlo, g_yn_lo);

    cudaFuncSetAttribute(gemm_bf3, cudaFuncAttributeMaxDynamicSharedMemorySize, GEMM_SMEM_BYTES);

    cvt_split<<<dim3(HIDDEN / 2 / 256, LSEQ), 256>>>(hidden, p_hhi, p_hlo, LSEQ, HIDDEN);
    cvt_split<<<dim3(HIDDEN / 2 / 256, W1_RPAD), 256>>>(in_proj_w, p_w1hi, p_w1lo, PROJ, HIDDEN);
    cvt_split<<<dim3(INTER / 2 / 256, HIDDEN), 256>>>(out_proj_w, p_w2hi, p_w2lo, HIDDEN, INTER);

    // GEMM1: proj = hidden @ in_proj_w^T : M=2048, N=8384 (pad 8448), K=2048
    gemm_bf3<<<dim3(W1_RPAD / BN, LSEQ / BM), 256, GEMM_SMEM_BYTES>>>(
        p_hhi, p_hlo, p_w1hi, p_w1lo, p_proj, LSEQ, PROJ, HIDDEN);

    {
        int total = LSEQ * (CONV_DIM + HEADS);
        conv_dt_kernel<<<(total + 255) / 256, 256>>>(conv_w, conv_b, dt_bias, A_log);
    }
    scan_kernel<<<HEADS * 2, 256>>>(Dv);
    norm_gate_cvt<<<LSEQ, 256>>>(norm_w);

    // GEMM2: out = y' @ out_proj_w^T : M=2048, N=2048, K=4096
    gemm_bf3<<<dim3(HIDDEN / BN, LSEQ / BM), 256, GEMM_SMEM_BYTES>>>(
        p_ynhi, p_ynlo, p_w2hi, p_w2lo, out, LSEQ, HIDDEN, INTER);
}

// round 14
// speedup vs baseline: 1.1565x; 1.0859x over previous
#include <cuda_runtime.h>
#include <cuda_bf16.h>
#include <cstdint>
#include <math.h>

#define LSEQ     2048
#define HIDDEN   2048
#define INTER    4096
#define HEADS    64
#define HEAD_DIM 64
#define STATE    64
#define KCONV    4
#define CONV_DIM (INTER + 2 * STATE)            // 4224
#define PROJ     (INTER + CONV_DIM + HEADS)     // 8384
#define W1_RPAD  8448                           // PROJ padded to 128

// ---------------- scratch ------------------------------------------------
__device__ float g_proj[(size_t)LSEQ * PROJ];
__device__ float g_conv[(size_t)LSEQ * CONV_DIM];
__device__ float g_y[(size_t)LSEQ * INTER];      // scan partial (n 0..31)
__device__ float g_y2[(size_t)LSEQ * INTER];     // scan partial (n 32..63)
__device__ float g_dtv[LSEQ * HEADS];
__device__ float g_dA[LSEQ * HEADS];
// bf16 split operands (u32 = packed bf16 pair, k-permuted layout)
__device__ uint32_t g_h_hi[(size_t)LSEQ * (HIDDEN / 2)];
__device__ uint32_t g_h_lo[(size_t)LSEQ * (HIDDEN / 2)];
__device__ uint32_t g_w1_hi[(size_t)W1_RPAD * (HIDDEN / 2)];
__device__ uint32_t g_w1_lo[(size_t)W1_RPAD * (HIDDEN / 2)];
__device__ uint32_t g_w2_hi[(size_t)HIDDEN * (INTER / 2)];
__device__ uint32_t g_w2_lo[(size_t)HIDDEN * (INTER / 2)];
__device__ uint32_t g_yn_hi[(size_t)LSEQ * (INTER / 2)];
__device__ uint32_t g_yn_lo[(size_t)LSEQ * (INTER / 2)];

// ---------------- helpers --------------------------------------------------
__device__ __forceinline__ void split_pack(float x0, float x1, uint32_t& hi, uint32_t& lo) {
    __nv_bfloat16 h0 = __float2bfloat16(x0);
    __nv_bfloat16 h1 = __float2bfloat16(x1);
    __nv_bfloat16 l0 = __float2bfloat16(x0 - __bfloat162float(h0));
    __nv_bfloat16 l1 = __float2bfloat16(x1 - __bfloat162float(h1));
    hi = (uint32_t)__bfloat16_as_ushort(h0) | ((uint32_t)__bfloat16_as_ushort(h1) << 16);
    lo = (uint32_t)__bfloat16_as_ushort(l0) | ((uint32_t)__bfloat16_as_ushort(l1) << 16);
}

__device__ __forceinline__ void mma_bf16(float* d, const uint32_t* a, const uint32_t* b) {
    asm volatile(
        "mma.sync.aligned.m16n8k16.row.col.f32.bf16.bf16.f32 "
        "{%0,%1,%2,%3}, {%4,%5,%6,%7}, {%8,%9}, {%0,%1,%2,%3};"
        : "+f"(d[0]), "+f"(d[1]), "+f"(d[2]), "+f"(d[3])
        : "r"(a[0]), "r"(a[1]), "r"(a[2]), "r"(a[3]), "r"(b[0]), "r"(b[1]));
}

__device__ __forceinline__ uint32_t smem_u32p(const void* p) {
    uint32_t a;
    asm("{ .reg .u64 t; cvta.to.shared.u64 t, %1; cvt.u32.u64 %0, t; }" : "=r"(a) : "l"(p));
    return a;
}
__device__ __forceinline__ void cp16(uint32_t dst, const void* src) {
    asm volatile("cp.async.cg.shared.global [%0], [%1], 16;" :: "r"(dst), "l"(src));
}
__device__ __forceinline__ void cp_commit() { asm volatile("cp.async.commit_group;"); }
__device__ __forceinline__ void cp_wait1()  { asm volatile("cp.async.wait_group 1;" ::: "memory"); }
__device__ __forceinline__ void cp_wait0()  { asm volatile("cp.async.wait_group 0;" ::: "memory"); }

// ---------------- convert f32 -> permuted bf16 hi/lo pairs (R5 layout) -----
__global__ void cvt_split(const float* __restrict__ in, uint32_t* __restrict__ hi,
                          uint32_t* __restrict__ lo, int R, int K)
{
    const int K2 = K >> 1;
    int jj  = blockIdx.x * blockDim.x + threadIdx.x;
    int row = blockIdx.y;
    if (jj >= K2) return;
    int g = jj >> 3, p = jj & 7;
    int jl = (g << 3) + (p >> 1) + ((p & 1) << 2);
    float a0 = 0.f, a1 = 0.f;
    if (row < R) {
        a0 = in[(size_t)row * K + 2 * jl];
        a1 = in[(size_t)row * K + 2 * jl + 1];
    }
    uint32_t h, l;
    split_pack(a0, a1, h, l);
    hi[(size_t)row * K2 + jj] = h;
    lo[(size_t)row * K2 + jj] = l;
}

// ---------------- bf16x3 GEMM (R10 measured best, unchanged) ----------------
#define BM 128
#define BN 128
#define BKE 32
#define BUF_U32 (BM * 16)              // 2048
#define STAGE_U32 (4 * BUF_U32)        // 8192
#define GEMM_SMEM_BYTES (3 * STAGE_U32 * 4)   // 98304

__global__ __launch_bounds__(256, 2) void gemm_bf3(
    const uint32_t* __restrict__ Ahi, const uint32_t* __restrict__ Alo,
    const uint32_t* __restrict__ Bhi, const uint32_t* __restrict__ Blo,
    float* __restrict__ C, int M, int N, int K)
{
    extern __shared__ uint32_t dsm[];
    const int K2  = K >> 1;
    const int nst = K / BKE;
    const int tid  = threadIdx.x;
    const int wid  = tid >> 5;
    const int lane = tid & 31;
    const int wm   = wid & 1;
    const int wn   = wid >> 1;
    const int m0   = blockIdx.y * BM;
    const int n0   = blockIdx.x * BN;
    const int lg   = lane >> 2;
    const int lc   = lane & 3;

    const uint32_t sbase = smem_u32p(dsm);
    const int crow = tid >> 1;
    const int cj   = (tid & 1) * 2;
    const int rsw  = (crow >> 1) & 1;

    float acc[4][4][4];
#pragma unroll
    for (int i = 0; i < 4; ++i)
#pragma unroll
        for (int j = 0; j < 4; ++j)
#pragma unroll
            for (int q = 0; q < 4; ++q) acc[i][j][q] = 0.f;

    auto issue = [&](int s) {
        const uint32_t st = sbase + ((s % 3) * STAGE_U32) * 4;
        const size_t ga = (size_t)(m0 + crow) * K2 + (size_t)s * 16;
        const size_t gb = (size_t)(n0 + crow) * K2 + (size_t)s * 16;
#pragma unroll
        for (int c = 0; c < 2; ++c) {
            const int j  = cj + (c ^ rsw);
            const int jp = j ^ (crow & 3);
            const uint32_t d = st + (crow * 16 + jp * 4) * 4;
            cp16(d,                    Ahi + ga + j * 4);
            cp16(d + BUF_U32 * 4,      Alo + ga + j * 4);
            cp16(d + 2 * BUF_U32 * 4,  Bhi + gb + j * 4);
            cp16(d + 3 * BUF_U32 * 4,  Blo + gb + j * 4);
        }
    };

    issue(0); cp_commit();
    issue(1); cp_commit();

    for (int s = 0; s < nst; ++s) {
        if (s < nst - 1) cp_wait1(); else cp_wait0();
        __syncthreads();
        if (s + 2 < nst) { issue(s + 2); cp_commit(); }

        const uint32_t* st   = dsm + (s % 3) * STAGE_U32;
        const uint32_t* pAhi = st;
        const uint32_t* pAlo = st + BUF_U32;
        const uint32_t* pBhi = st + 2 * BUF_U32;
        const uint32_t* pBlo = st + 3 * BUF_U32;

#pragma unroll
        for (int ks = 0; ks < 2; ++ks) {
            const int jw = ks * 8 + 2 * lc;
            uint2 aH0[4], aH1[4], aL0[4], aL1[4], bH[4], bL[4];
#pragma unroll
            for (int mt = 0; mt < 4; ++mt) {
                int r0 = wm * 64 + mt * 16 + lg;
                int sx = (r0 & 3) << 2;
                int o0 = r0 * 16 + (jw ^ sx);
                int o1 = (r0 + 8) * 16 + (jw ^ sx);
                aH0[mt] = *reinterpret_cast<const uint2*>(pAhi + o0);
                aH1[mt] = *reinterpret_cast<const uint2*>(pAhi + o1);
                aL0[mt] = *reinterpret_cast<const uint2*>(pAlo + o0);
                aL1[mt] = *reinterpret_cast<const uint2*>(pAlo + o1);
            }
#pragma unroll
            for (int nt = 0; nt < 4; ++nt) {
                int rb = wn * 32 + nt * 8 + lg;
                int ob = rb * 16 + (jw ^ ((rb & 3) << 2));
                bH[nt] = *reinterpret_cast<const uint2*>(pBhi + ob);
                bL[nt] = *reinterpret_cast<const uint2*>(pBlo + ob);
            }
#pragma unroll
            for (int mt = 0; mt < 4; ++mt) {
                uint32_t ah[4] = {aH0[mt].x, aH1[mt].x, aH0[mt].y, aH1[mt].y};
#pragma unroll
                for (int nt = 0; nt < 4; ++nt) {
                    uint32_t bh[2] = {bH[nt].x, bH[nt].y};
                    mma_bf16(acc[mt][nt], ah, bh);
                }
            }
#pragma unroll
            for (int mt = 0; mt < 4; ++mt) {
                uint32_t ah[4] = {aH0[mt].x, aH1[mt].x, aH0[mt].y, aH1[mt].y};
#pragma unroll
                for (int nt = 0; nt < 4; ++nt) {
                    uint32_t bl[2] = {bL[nt].x, bL[nt].y};
                    mma_bf16(acc[mt][nt], ah, bl);
                }
            }
#pragma unroll
            for (int mt = 0; mt < 4; ++mt) {
                uint32_t al[4] = {aL0[mt].x, aL1[mt].x, aL0[mt].y, aL1[mt].y};
#pragma unroll
                for (int nt = 0; nt < 4; ++nt) {
                    uint32_t bh[2] = {bH[nt].x, bH[nt].y};
                    mma_bf16(acc[mt][nt], al, bh);
                }
            }
        }
    }

#pragma unroll
    for (int mt = 0; mt < 4; ++mt) {
        int r0 = m0 + wm * 64 + mt * 16 + lg;
#pragma unroll
        for (int nt = 0; nt < 4; ++nt) {
            int gc = n0 + wn * 32 + nt * 8 + lc * 2;
            if (gc < N) {
                *reinterpret_cast<float2*>(&C[(size_t)r0 * N + gc]) =
                    make_float2(acc[mt][nt][0], acc[mt][nt][1]);
                *reinterpret_cast<float2*>(&C[(size_t)(r0 + 8) * N + gc]) =
                    make_float2(acc[mt][nt][2], acc[mt][nt][3]);
            }
        }
    }
}

// ---------------- fused conv+silu and dt transform --------------------------
__global__ void conv_dt_kernel(const float* __restrict__ conv_w,
                               const float* __restrict__ conv_b,
                               const float* __restrict__ dt_bias,
                               const float* __restrict__ A_log)
{
    int idx = blockIdx.x * blockDim.x + threadIdx.x;
    if (idx < LSEQ * CONV_DIM) {
        int c = idx % CONV_DIM;
        int t = idx / CONV_DIM;
        const float4 w = *reinterpret_cast<const float4*>(&conv_w[c * 4]);
        const float* col = g_proj + INTER + c;
        float acc = conv_b[c];
        if (t - 3 >= 0) acc = fmaf(col[(size_t)(t - 3) * PROJ], w.x, acc);
        if (t - 2 >= 0) acc = fmaf(col[(size_t)(t - 2) * PROJ], w.y, acc);
        if (t - 1 >= 0) acc = fmaf(col[(size_t)(t - 1) * PROJ], w.z, acc);
        acc = fmaf(col[(size_t)t * PROJ], w.w, acc);
        g_conv[idx] = acc / (1.f + expf(-acc));
    } else {
        int j = idx - LSEQ * CONV_DIM;
        if (j >= LSEQ * HEADS) return;
        int h = j & (HEADS - 1);
        int t = j >> 6;
        float z = g_proj[(size_t)t * PROJ + INTER + CONV_DIM + h] + dt_bias[h];
        float d = (z > 20.f) ? z : log1pf(expf(z));
        float A = -expf(A_log[h]);
        g_dtv[j] = d;
        g_dA[j]  = expf(d * A);
    }
}

// ---------------- selective scan v3 (measured best, R10 verbatim) ------------
#define TCH 8
#define NCH (LSEQ / TCH)
__global__ __launch_bounds__(128) void scan_kernel(const float* __restrict__ D)
{
    const int h   = blockIdx.x >> 2;
    const int ph  = (blockIdx.x >> 1) & 1;
    const int nh  = blockIdx.x & 1;
    const int tid = threadIdx.x;
    const int pl  = tid >> 2;
    const int q   = tid & 3;
    const int n0  = q * 8;
    const float Dh = D[h];
    float* yout = nh ? g_y2 : g_y;

    __shared__ float sB[2][TCH][32], sC[2][TCH][32], sX[2][TCH][32];
    __shared__ float sDT[2][TCH], sDA[2][TCH];

    const int tl   = tid >> 4;
    const int col2 = tid & 15;

    {
        const float* rowp = g_conv + (size_t)tl * CONV_DIM;
        *reinterpret_cast<float2*>(&sB[0][tl][col2 * 2]) =
            *reinterpret_cast<const float2*>(&rowp[INTER + nh * 32 + col2 * 2]);
        *reinterpret_cast<float2*>(&sC[0][tl][col2 * 2]) =
            *reinterpret_cast<const float2*>(&rowp[INTER + STATE + nh * 32 + col2 * 2]);
        *reinterpret_cast<float2*>(&sX[0][tl][col2 * 2]) =
            *reinterpret_cast<const float2*>(&rowp[h * HEAD_DIM + ph * 32 + col2 * 2]);
        if (tid < TCH)           sDT[0][tid]       = g_dtv[tid * HEADS + h];
        else if (tid < 2 * TCH)  sDA[0][tid - TCH] = g_dA[(tid - TCH) * HEADS + h];
    }
    __syncthreads();

    float s[8];
#pragma unroll
    for (int i = 0; i < 8; ++i) s[i] = 0.f;

    for (int c = 0; c < NCH; ++c) {
        const int buf = c & 1;
        const int t0  = c * TCH;
        const bool more = (c + 1 < NCH);

        float2 nB, nC, nX; float nS = 0.f;
        if (more) {
            const float* rowp = g_conv + (size_t)(t0 + TCH + tl) * CONV_DIM;
            nB = *reinterpret_cast<const float2*>(&rowp[INTER + nh * 32 + col2 * 2]);
            nC = *reinterpret_cast<const float2*>(&rowp[INTER + STATE + nh * 32 + col2 * 2]);
            nX = *reinterpret_cast<const float2*>(&rowp[h * HEAD_DIM + ph * 32 + col2 * 2]);
            if (tid < TCH)           nS = g_dtv[(t0 + TCH + tid) * HEADS + h];
            else if (tid < 2 * TCH)  nS = g_dA[(t0 + TCH + tid - TCH) * HEADS + h];
        }

#pragma unroll
        for (int k = 0; k < TCH; ++k) {
            const float a   = sDA[buf][k];
            const float dtv = sDT[buf][k];
            const float xv  = sX[buf][k][pl];
            const float dtx = dtv * xv;
            float4 b0 = *reinterpret_cast<const float4*>(&sB[buf][k][n0]);
            float4 b1 = *reinterpret_cast<const float4*>(&sB[buf][k][n0 + 4]);
            float4 c0 = *reinterpret_cast<const float4*>(&sC[buf][k][n0]);
            float4 c1 = *reinterpret_cast<const float4*>(&sC[buf][k][n0 + 4]);
            s[0] = fmaf(a, s[0], dtx * b0.x);
            s[1] = fmaf(a, s[1], dtx * b0.y);
            s[2] = fmaf(a, s[2], dtx * b0.z);
            s[3] = fmaf(a, s[3], dtx * b0.w);
            s[4] = fmaf(a, s[4], dtx * b1.x);
            s[5] = fmaf(a, s[5], dtx * b1.y);
            s[6] = fmaf(a, s[6], dtx * b1.z);
            s[7] = fmaf(a, s[7], dtx * b1.w);
            float e0 = fmaf(s[1], c0.y, s[0] * c0.x);
            float e1 = fmaf(s[3], c0.w, s[2] * c0.z);
            float e2 = fmaf(s[5], c1.y, s[4] * c1.x);
            float e3 = fmaf(s[7], c1.w, s[6] * c1.z);
            float accv = (e0 + e1) + (e2 + e3);
            accv += __shfl_xor_sync(0xffffffffu, accv, 1);
            accv += __shfl_xor_sync(0xffffffffu, accv, 2);
            if (q == 0) {
                float o = accv + (nh == 0 ? Dh * xv : 0.f);
                yout[(size_t)(t0 + k) * INTER + h * HEAD_DIM + ph * 32 + pl] = o;
            }
        }

        if (more) {
            const int nb = buf ^ 1;
            *reinterpret_cast<float2*>(&sB[nb][tl][col2 * 2]) = nB;
            *reinterpret_cast<float2*>(&sC[nb][tl][col2 * 2]) = nC;
            *reinterpret_cast<float2*>(&sX[nb][tl][col2 * 2]) = nX;
            if (tid < TCH)           sDT[nb][tid]       = nS;
            else if (tid < 2 * TCH)  sDA[nb][tid - TCH] = nS;
        }
        __syncthreads();
    }
}

// ---------------- RMSNorm * silu(gate) -> bf16 hi/lo (R10 verbatim) ----------
__global__ __launch_bounds__(256) void norm_gate_cvt(const float* __restrict__ nw)
{
    const int t = blockIdx.x;
    const float* y1 = g_y  + (size_t)t * INTER;
    const float* y2 = g_y2 + (size_t)t * INTER;
    const float* gp = g_proj + (size_t)t * PROJ;
    __shared__ float red[256];
    float ss = 0.f;
    for (int c = threadIdx.x; c < INTER; c += 256) {
        float v = y1[c] + y2[c];
        ss = fmaf(v, v, ss);
    }
    red[threadIdx.x] = ss;
    __syncthreads();
    for (int off = 128; off > 0; off >>= 1) {
        if (threadIdx.x < off) red[threadIdx.x] += red[threadIdx.x + off];
        __syncthreads();
    }
    const float r = rsqrtf(red[0] / (float)INTER + 1e-6f);

    const int K2 = INTER / 2;
    for (int J = threadIdx.x; J < K2; J += 256) {
        int g = J >> 3, p = J & 7;
        int jl = (g << 3) + (p >> 1) + ((p & 1) << 2);
        int c0 = 2 * jl;
        float ga = gp[c0], gb = gp[c0 + 1];
        float v0 = (y1[c0] + y2[c0]) * r * nw[c0] * (ga / (1.f + expf(-ga)));
        float v1 = (y1[c0 + 1] + y2[c0 + 1]) * r * nw[c0 + 1] * (gb / (1.f + expf(-gb)));
        uint32_t h, l;
        split_pack(v0, v1, h, l);
        g_yn_hi[(size_t)t * K2 + J] = h;
        g_yn_lo[(size_t)t * K2 + J] = l;
    }
}

// ---------------- launch ------------------------------------------------------
extern "C" void kernel_launch(void* const* d_in, const int* in_sizes, int n_in,
                              void* d_out, int out_size)
{
    const float* hidden     = (const float*)d_in[0];
    const float* in_proj_w  = (const float*)d_in[1];
    const float* conv_w     = (const float*)d_in[2];
    const float* conv_b     = (const float*)d_in[3];
    const float* dt_bias    = (const float*)d_in[4];
    const float* A_log      = (const float*)d_in[5];
    const float* Dv         = (const float*)d_in[6];
    const float* norm_w     = (const float*)d_in[7];
    const float* out_proj_w = (const float*)d_in[8];
    float* out = (float*)d_out;

    float* p_proj = nullptr;
    cudaGetSymbolAddress((void**)&p_proj, g_proj);
    uint32_t *p_hhi, *p_hlo, *p_w1hi, *p_w1lo, *p_w2hi, *p_w2lo, *p_ynhi, *p_ynlo;
    cudaGetSymbolAddress((void**)&p_hhi, g_h_hi);
    cudaGetSymbolAddress((void**)&p_hlo, g_h_lo);
    cudaGetSymbolAddress((void**)&p_w1hi, g_w1_hi);
    cudaGetSymbolAddress((void**)&p_w1lo, g_w1_lo);
    cudaGetSymbolAddress((void**)&p_w2hi, g_w2_hi);
    cudaGetSymbolAddress((void**)&p_w2lo, g_w2_lo);
    cudaGetSymbolAddress((void**)&p_ynhi, g_yn_hi);
    cudaGetSymbolAddress((void**)&p_ynlo, g_yn_lo);

    cudaFuncSetAttribute(gemm_bf3, cudaFuncAttributeMaxDynamicSharedMemorySize, GEMM_SMEM_BYTES);

    // operand converts needed before GEMM1
    cvt_split<<<dim3(HIDDEN / 2 / 256, LSEQ), 256>>>(hidden, p_hhi, p_hlo, LSEQ, HIDDEN);
    cvt_split<<<dim3(HIDDEN / 2 / 256, W1_RPAD), 256>>>(in_proj_w, p_w1hi, p_w1lo, PROJ, HIDDEN);

    // GEMM1: proj = hidden @ in_proj_w^T : M=2048, N=8384 (pad 8448), K=2048
    gemm_bf3<<<dim3(W1_RPAD / BN, LSEQ / BM), 256, GEMM_SMEM_BYTES>>>(
        p_hhi, p_hlo, p_w1hi, p_w1lo, p_proj, LSEQ, PROJ, HIDDEN);

    // fork: w2 conversion overlaps with latency-bound conv/dt/scan branch
    cudaStream_t s1;
    cudaStreamCreateWithFlags(&s1, cudaStreamNonBlocking);
    cudaEvent_t evA, evB;
    cudaEventCreateWithFlags(&evA, cudaEventDisableTiming);
    cudaEventCreateWithFlags(&evB, cudaEventDisableTiming);

    cudaEventRecord(evA, 0);
    cudaStreamWaitEvent(s1, evA, 0);
    cvt_split<<<dim3(INTER / 2 / 256, HIDDEN), 256, 0, s1>>>(out_proj_w, p_w2hi, p_w2lo, HIDDEN, INTER);
    cudaEventRecord(evB, s1);

    // scan branch (legacy stream)
    {
        int total = LSEQ * (CONV_DIM + HEADS);
        conv_dt_kernel<<<(total + 255) / 256, 256>>>(conv_w, conv_b, dt_bias, A_log);
    }
    scan_kernel<<<HEADS * 4, 128>>>(Dv);
    norm_gate_cvt<<<LSEQ, 256>>>(norm_w);

    // join before GEMM2 (needs w2 converts + yn)
    cudaStreamWaitEvent(0, evB, 0);

    // GEMM2: out = y' @ out_proj_w^T : M=2048, N=2048, K=4096
    gemm_bf3<<<dim3(HIDDEN / BN, LSEQ / BM), 256, GEMM_SMEM_BYTES>>>(
        p_ynhi, p_ynlo, p_w2hi, p_w2lo, out, LSEQ, HIDDEN, INTER);

    cudaEventDestroy(evA);
    cudaEventDestroy(evB);
    cudaStreamDestroy(s1);
}